// round 9
// baseline (speedup 1.0000x reference)
#include <cuda_runtime.h>
#include <cuda_fp16.h>
#include <cstdint>
#include <math.h>

#define BB 4
#define SS 4096
#define DD 1024
#define DQK 64

// ---------------- scratch (alloc-free: __device__ globals) ----------------
static __device__ float  g_Q[BB * SS * DQK];            // 4 MB (pre-scaled by 1/8)
static __device__ float  g_K[BB * SS * DQK];            // 4 MB
static __device__ float  g_P[(size_t)BB * SS * SS];     // 268 MB raw scores
static __device__ __half g_Ph[(size_t)BB * SS * SS];    // 134 MB normalized P (fp16)
static __device__ __half g_Vh[(size_t)BB * SS * DD];    // 33.5 MB enc hi fp16
static __device__ __half g_Vl[(size_t)BB * SS * DD];    // 33.5 MB enc lo fp16
static __device__ float  g_m[BB * SS];
static __device__ float  g_l[BB * SS];

// =====================================================================
// Kernel 1: fused Q/K projection (scalar, 8x8 micro-tile, 128 threads)
// =====================================================================
__global__ __launch_bounds__(128) void proj_kernel(const float* __restrict__ enc,
                                                   const float* __restrict__ Wq,
                                                   const float* __restrict__ Wk) {
    __shared__ float As[32][68];
    __shared__ float Ws[32][132];
    const int m0 = blockIdx.x * 64;
    const int tid = threadIdx.x;
    const int tx = tid & 15;    // 16 col groups x 8 cols
    const int ty = tid >> 4;    // 8 row groups x 8 rows

    float acc[8][8];
#pragma unroll
    for (int i = 0; i < 8; i++) {
#pragma unroll
        for (int j = 0; j < 8; j++) { acc[i][j] = 0.0f; }
    }

    for (int k0 = 0; k0 < DD; k0 += 32) {
        // A tile: 64 rows x 32 k  (512 float4, 4 per thread)
#pragma unroll
        for (int t = 0; t < 4; t++) {
            int f = tid + t * 128;
            int r = f >> 3;
            int c4 = f & 7;
            float4 v = *(const float4*)&enc[(size_t)(m0 + r) * DD + k0 + c4 * 4];
            As[c4 * 4 + 0][r] = v.x;
            As[c4 * 4 + 1][r] = v.y;
            As[c4 * 4 + 2][r] = v.z;
            As[c4 * 4 + 3][r] = v.w;
        }
        // W tile: 128 cols x 32 k  (1024 float4, 8 per thread)
#pragma unroll
        for (int t = 0; t < 8; t++) {
            int f = tid + t * 128;
            int col = f >> 3;
            int c4 = f & 7;
            const float* src;
            if (col < 64) { src = &Wq[(size_t)col * DD + k0 + c4 * 4]; }
            else          { src = &Wk[(size_t)(col - 64) * DD + k0 + c4 * 4]; }
            float4 v = *(const float4*)src;
            Ws[c4 * 4 + 0][col] = v.x;
            Ws[c4 * 4 + 1][col] = v.y;
            Ws[c4 * 4 + 2][col] = v.z;
            Ws[c4 * 4 + 3][col] = v.w;
        }
        __syncthreads();
#pragma unroll
        for (int kk = 0; kk < 32; kk++) {
            float a[8];
            float w[8];
#pragma unroll
            for (int i = 0; i < 8; i++) { a[i] = As[kk][ty * 8 + i]; }
#pragma unroll
            for (int j = 0; j < 8; j++) { w[j] = Ws[kk][tx * 8 + j]; }
#pragma unroll
            for (int i = 0; i < 8; i++) {
#pragma unroll
                for (int j = 0; j < 8; j++) { acc[i][j] = fmaf(a[i], w[j], acc[i][j]); }
            }
        }
        __syncthreads();
    }
#pragma unroll
    for (int i = 0; i < 8; i++) {
        int row = m0 + ty * 8 + i;
#pragma unroll
        for (int j = 0; j < 8; j++) {
            int col = tx * 8 + j;
            if (col < 64) { g_Q[(size_t)row * DQK + col] = acc[i][j] * 0.125f; }
            else          { g_K[(size_t)row * DQK + (col - 64)] = acc[i][j]; }
        }
    }
}

// =====================================================================
// Kernel 2: enc -> fp16 hi/lo split (one-time V conversion)
// =====================================================================
__global__ __launch_bounds__(256) void vconv_kernel(const float* __restrict__ enc) {
    const size_t n = (size_t)BB * SS * DD;
    size_t i = ((size_t)blockIdx.x * 256 + threadIdx.x) * 4;
    const size_t step = (size_t)gridDim.x * 256 * 4;
    for (; i < n; i += step) {
        float4 v = *(const float4*)&enc[i];
        __half2 h01 = __floats2half2_rn(v.x, v.y);
        __half2 h23 = __floats2half2_rn(v.z, v.w);
        float2 r01 = __half22float2(h01);
        float2 r23 = __half22float2(h23);
        __half2 l01 = __floats2half2_rn(v.x - r01.x, v.y - r01.y);
        __half2 l23 = __floats2half2_rn(v.z - r23.x, v.w - r23.y);
        *(__half2*)&g_Vh[i] = h01;
        *(__half2*)&g_Vh[i + 2] = h23;
        *(__half2*)&g_Vl[i] = l01;
        *(__half2*)&g_Vl[i + 2] = l23;
    }
}

// =====================================================================
// Kernel 3: raw scores + online row stats (scalar). Masked = -1e9,
// written over the 128-padded causal span.
// =====================================================================
__global__ __launch_bounds__(256) void score_kernel() {
    const int qt = (int)gridDim.x - 1 - (int)blockIdx.x;
    const int b = blockIdx.y;
    const int q0 = qt * 64;
    const int tid = threadIdx.x;
    const int tx = tid & 15;
    const int ty = tid >> 4;

    __shared__ float Qs[64][68];
    __shared__ float Ks[64][68];
    __shared__ float red_m[64][16];
    __shared__ float red_l[64][16];

#pragma unroll
    for (int t = 0; t < 4; t++) {
        int f = tid + t * 256;
        int r = f >> 4;
        int e4 = f & 15;
        float4 v = *(const float4*)&g_Q[(size_t)(b * SS + q0 + r) * DQK + e4 * 4];
        Qs[e4 * 4 + 0][r] = v.x;
        Qs[e4 * 4 + 1][r] = v.y;
        Qs[e4 * 4 + 2][r] = v.z;
        Qs[e4 * 4 + 3][r] = v.w;
    }

    float m_i[4];
    float l_i[4];
#pragma unroll
    for (int i = 0; i < 4; i++) { m_i[i] = -INFINITY; l_i[i] = 0.0f; }

    const int kt_end = (qt | 1);
    for (int kt = 0; kt <= kt_end; kt++) {
        const int k0 = kt * 64;
        __syncthreads();
#pragma unroll
        for (int t = 0; t < 4; t++) {
            int f = tid + t * 256;
            int r = f >> 4;
            int e4 = f & 15;
            float4 v = *(const float4*)&g_K[(size_t)(b * SS + k0 + r) * DQK + e4 * 4];
            Ks[e4 * 4 + 0][r] = v.x;
            Ks[e4 * 4 + 1][r] = v.y;
            Ks[e4 * 4 + 2][r] = v.z;
            Ks[e4 * 4 + 3][r] = v.w;
        }
        __syncthreads();

        float acc[4][4];
#pragma unroll
        for (int i = 0; i < 4; i++) {
#pragma unroll
            for (int j = 0; j < 4; j++) { acc[i][j] = 0.0f; }
        }

#pragma unroll
        for (int e = 0; e < 64; e++) {
            float4 a = *(const float4*)&Qs[e][ty * 4];
            float4 kb = *(const float4*)&Ks[e][tx * 4];
            float av[4];
            float bv[4];
            av[0] = a.x; av[1] = a.y; av[2] = a.z; av[3] = a.w;
            bv[0] = kb.x; bv[1] = kb.y; bv[2] = kb.z; bv[3] = kb.w;
#pragma unroll
            for (int i = 0; i < 4; i++) {
#pragma unroll
                for (int j = 0; j < 4; j++) { acc[i][j] = fmaf(av[i], bv[j], acc[i][j]); }
            }
        }

#pragma unroll
        for (int i = 0; i < 4; i++) {
            const int q = q0 + ty * 4 + i;
            float sv[4];
#pragma unroll
            for (int j = 0; j < 4; j++) {
                int kj = k0 + tx * 4 + j;
                sv[j] = (kj <= q) ? acc[i][j] : -1e9f;
            }
            float tmax = fmaxf(fmaxf(sv[0], sv[1]), fmaxf(sv[2], sv[3]));
            float nm = fmaxf(m_i[i], tmax);
            float l = l_i[i] * __expf(m_i[i] - nm);
#pragma unroll
            for (int j = 0; j < 4; j++) { l += __expf(sv[j] - nm); }
            m_i[i] = nm;
            l_i[i] = l;
            *(float4*)&g_P[((size_t)(b * SS + q)) * SS + k0 + tx * 4] =
                make_float4(sv[0], sv[1], sv[2], sv[3]);
        }
    }

#pragma unroll
    for (int i = 0; i < 4; i++) {
        red_m[ty * 4 + i][tx] = m_i[i];
        red_l[ty * 4 + i][tx] = l_i[i];
    }
    __syncthreads();
    if (tid < 64) {
        int row = tid;
        float M = -INFINITY;
#pragma unroll
        for (int t = 0; t < 16; t++) { M = fmaxf(M, red_m[row][t]); }
        float L = 0.0f;
#pragma unroll
        for (int t = 0; t < 16; t++) { L += red_l[row][t] * __expf(red_m[row][t] - M); }
        g_m[b * SS + q0 + row] = M;
        g_l[b * SS + q0 + row] = L;
    }
}

// =====================================================================
// Kernel 4: P convert  (raw S fp32 -> normalized P fp16, causal span)
// =====================================================================
__global__ __launch_bounds__(256) void pconv_kernel() {
    const int qt = blockIdx.x;
    const int b = blockIdx.y;
    const int q0 = qt * 64;
    const int ncols = ((qt | 1) + 1) * 64;
    const int tid = threadIdx.x;

    for (int r = 0; r < 64; r++) {
        const int row = q0 + r;
        const float m = g_m[b * SS + row];
        const float invl = 1.0f / g_l[b * SS + row];
        const float* src = &g_P[((size_t)(b * SS + row)) * SS];
        __half* dst = &g_Ph[((size_t)(b * SS + row)) * SS];
        for (int c = tid * 4; c < ncols; c += 1024) {
            float4 v = *(const float4*)&src[c];
            __half2 h01 = __floats2half2_rn(__expf(v.x - m) * invl, __expf(v.y - m) * invl);
            __half2 h23 = __floats2half2_rn(__expf(v.z - m) * invl, __expf(v.w - m) * invl);
            *(__half2*)&dst[c] = h01;
            *(__half2*)&dst[c + 2] = h23;
        }
    }
}

// =====================================================================
// Kernel 5: tensor-core PV.  O = P(fp16) @ (Vh + Vl),  cp.async pipeline.
// =====================================================================
#define PSTR 40     // halfs per P smem row (80 B)
#define VSTR 136    // halfs per V smem row (272 B)
// smem half-offsets: P stages at 0/5120, Vh at 10240/14592, Vl at 18944/23296
#define PV_SMEM_BYTES 55296

__device__ __forceinline__ void cp16(uint32_t dst, const void* src) {
    asm volatile(
        "{\n\t"
        ".reg .u64 gp;\n\t"
        "cvta.to.global.u64 gp, %1;\n\t"
        "cp.async.ca.shared.global [%0], [gp], 16;\n\t"
        "}"
        :: "r"(dst), "l"(src) : "memory");
}

__device__ __forceinline__ void ldsm4(uint32_t* r, const void* p) {
    uint32_t a = (uint32_t)__cvta_generic_to_shared(p);
    asm volatile("ldmatrix.sync.aligned.m8n8.x4.shared.b16 {%0,%1,%2,%3}, [%4];"
                 : "=r"(r[0]), "=r"(r[1]), "=r"(r[2]), "=r"(r[3])
                 : "r"(a));
}

__device__ __forceinline__ void ldsm4t(uint32_t* r, const void* p) {
    uint32_t a = (uint32_t)__cvta_generic_to_shared(p);
    asm volatile("ldmatrix.sync.aligned.m8n8.x4.trans.shared.b16 {%0,%1,%2,%3}, [%4];"
                 : "=r"(r[0]), "=r"(r[1]), "=r"(r[2]), "=r"(r[3])
                 : "r"(a));
}

__device__ __forceinline__ void mma_f16(float* c, const uint32_t* a,
                                        uint32_t b0, uint32_t b1) {
    asm volatile(
        "mma.sync.aligned.m16n8k16.row.col.f32.f16.f16.f32 "
        "{%0,%1,%2,%3}, {%4,%5,%6,%7}, {%8,%9}, {%0,%1,%2,%3};"
        : "+f"(c[0]), "+f"(c[1]), "+f"(c[2]), "+f"(c[3])
        : "r"(a[0]), "r"(a[1]), "r"(a[2]), "r"(a[3]), "r"(b0), "r"(b1));
}

__device__ __forceinline__ void pv_load_stage(uint32_t smb, int st, int tid,
                                              const __half* gP,
                                              const __half* gVh,
                                              const __half* gVl) {
    const int pr = tid >> 1;
    const int pc = (tid & 1) * 16;
    uint32_t dP = smb + (uint32_t)((st * 5120 + pr * PSTR + pc) * 2);
    cp16(dP, gP + (size_t)pr * SS + pc);
    cp16(dP + 16, gP + (size_t)pr * SS + pc + 8);
    const int vk = tid >> 3;
    const int vc = (tid & 7) * 16;
    uint32_t dVh = smb + (uint32_t)((10240 + st * 4352 + vk * VSTR + vc) * 2);
    cp16(dVh, gVh + (size_t)vk * DD + vc);
    cp16(dVh + 16, gVh + (size_t)vk * DD + vc + 8);
    uint32_t dVl = smb + (uint32_t)((18944 + st * 4352 + vk * VSTR + vc) * 2);
    cp16(dVl, gVl + (size_t)vk * DD + vc);
    cp16(dVl + 16, gVl + (size_t)vk * DD + vc + 8);
}

__global__ __launch_bounds__(256, 2) void pv_kernel(float* __restrict__ out) {
    extern __shared__ __half sm[];
    const int ct = blockIdx.x;                               // dv tile 0..7
    const int rt = (int)gridDim.y - 1 - (int)blockIdx.y;     // heavy tiles first
    const int b  = blockIdx.z;
    const int q0 = rt * 128;
    const int c0 = ct * 128;
    const int tid = threadIdx.x;
    const int lane = tid & 31;
    const int wid = tid >> 5;
    const int wm = (wid & 3) * 32;
    const int wn = (wid >> 2) * 64;

    const uint32_t smb = (uint32_t)__cvta_generic_to_shared((void*)sm);

    float acc[2][8][4];
#pragma unroll
    for (int i = 0; i < 2; i++) {
#pragma unroll
        for (int j = 0; j < 8; j++) {
#pragma unroll
            for (int q = 0; q < 4; q++) { acc[i][j][q] = 0.0f; }
        }
    }

    const __half* gPbase = &g_Ph[((size_t)(b * SS + q0)) * SS];
    const __half* gVhbase = &g_Vh[((size_t)(b * SS)) * DD + c0];
    const __half* gVlbase = &g_Vl[((size_t)(b * SS)) * DD + c0];

    const int nk = (rt + 1) * 4;        // number of k32 steps

    pv_load_stage(smb, 0, tid, gPbase, gVhbase, gVlbase);
    asm volatile("cp.async.commit_group;" ::: "memory");

    for (int kt = 0; kt < nk; kt++) {
        const int st = kt & 1;
        if (kt + 1 < nk) {
            const int k1 = (kt + 1) * 32;
            pv_load_stage(smb, st ^ 1, tid, gPbase + k1,
                          gVhbase + (size_t)k1 * DD, gVlbase + (size_t)k1 * DD);
            asm volatile("cp.async.commit_group;" ::: "memory");
            asm volatile("cp.async.wait_group 1;" ::: "memory");
        } else {
            asm volatile("cp.async.wait_group 0;" ::: "memory");
        }
        __syncthreads();

        const __half* sP = sm + st * 5120;
        const __half* sVh = sm + 10240 + st * 4352;
        const __half* sVl = sm + 18944 + st * 4352;

#pragma unroll
        for (int s16 = 0; s16 < 2; s16++) {
            const int arow = lane & 15;
            const int ak = s16 * 16 + (lane >> 4) * 8;
            uint32_t ah0[4];
            uint32_t ah1[4];
            ldsm4(ah0, sP + (wm + arow) * PSTR + ak);
            ldsm4(ah1, sP + (wm + 16 + arow) * PSTR + ak);

#pragma unroll
            for (int nb = 0; nb < 4; nb++) {
                const int bofs = (s16 * 16 + (lane & 15)) * VSTR
                               + wn + nb * 16 + (lane >> 4) * 8;
                uint32_t bh[4];
                uint32_t bl[4];
                ldsm4t(bh, sVh + bofs);
                ldsm4t(bl, sVl + bofs);

                float* cp0 = acc[0][nb * 2];
                float* cp1 = acc[0][nb * 2 + 1];
                float* cp2 = acc[1][nb * 2];
                float* cp3 = acc[1][nb * 2 + 1];

                mma_f16(cp0, ah0, bh[0], bh[1]);
                mma_f16(cp0, ah0, bl[0], bl[1]);
                mma_f16(cp1, ah0, bh[2], bh[3]);
                mma_f16(cp1, ah0, bl[2], bl[3]);
                mma_f16(cp2, ah1, bh[0], bh[1]);
                mma_f16(cp2, ah1, bl[0], bl[1]);
                mma_f16(cp3, ah1, bh[2], bh[3]);
                mma_f16(cp3, ah1, bl[2], bl[3]);
            }
        }
        __syncthreads();
    }

    // epilogue
#pragma unroll
    for (int mi = 0; mi < 2; mi++) {
        const int r0 = q0 + wm + mi * 16 + (lane >> 2);
#pragma unroll
        for (int nb8 = 0; nb8 < 8; nb8++) {
            const int cc = c0 + wn + nb8 * 8 + (lane & 3) * 2;
            float2* o0 = (float2*)&out[((size_t)(b * SS + r0)) * DD + cc];
            float2* o1 = (float2*)&out[((size_t)(b * SS + r0 + 8)) * DD + cc];
            o0->x = acc[mi][nb8][0];
            o0->y = acc[mi][nb8][1];
            o1->x = acc[mi][nb8][2];
            o1->y = acc[mi][nb8][3];
        }
    }
}

// =====================================================================
extern "C" void kernel_launch(void* const* d_in, const int* in_sizes, int n_in,
                              void* d_out, int out_size) {
    (void)in_sizes; (void)n_in; (void)out_size;
    const float* enc = (const float*)d_in[0];
    const float* Wq  = (const float*)d_in[1];
    const float* Wk  = (const float*)d_in[2];
    float* out = (float*)d_out;

    cudaFuncSetAttribute(pv_kernel, cudaFuncAttributeMaxDynamicSharedMemorySize,
                         PV_SMEM_BYTES);

    proj_kernel<<<256, 128>>>(enc, Wq, Wk);
    vconv_kernel<<<1024, 256>>>(enc);
    score_kernel<<<dim3(SS / 64, BB), 256>>>();
    pconv_kernel<<<dim3(SS / 64, BB), 256>>>();
    pv_kernel<<<dim3(DD / 128, SS / 128, BB), 256, PV_SMEM_BYTES>>>(out);
}

// round 10
// speedup vs baseline: 1.7641x; 1.7641x over previous
#include <cuda_runtime.h>
#include <cuda_fp16.h>
#include <cstdint>
#include <math.h>

#define BB 4
#define SS 4096
#define DD 1024
#define DQK 64

// ---------------- scratch (alloc-free: __device__ globals) ----------------
static __device__ float  g_Q[BB * SS * DQK];            // 4 MB (pre-scaled by 1/8)
static __device__ float  g_K[BB * SS * DQK];            // 4 MB
static __device__ __half g_Ph[(size_t)BB * SS * SS];    // 134 MB unnormalized exp(s) fp16
static __device__ __half g_Vh[(size_t)BB * SS * DD];    // 33.5 MB enc hi fp16
static __device__ __half g_Vl[(size_t)BB * SS * DD];    // 33.5 MB enc lo fp16
static __device__ float  g_l[BB * SS];                  // row sums

// fast exp on the fma/alu pipes (no MUFU): exp(x) = 2^(x*log2e)
__device__ __forceinline__ float fexp(float x) {
    float t = fmaxf(x, -80.0f) * 1.44269504f;   // masked -1e9 -> t = -115.4
    float f = rintf(t);
    float r = t - f;
    float p = 1.0f + r * (0.69314718f + r * (0.24022651f + r * (0.05550411f
                  + r * (0.00961813f + r * 0.00133336f))));
    int e = (int)f;
    uint32_t bits = (uint32_t)(e + 127) << 23;
    return p * __uint_as_float(bits);
}

// =====================================================================
// Kernel 1: fused Q/K projection (scalar, 8x8 micro-tile, 128 threads)
// =====================================================================
__global__ __launch_bounds__(128) void proj_kernel(const float* __restrict__ enc,
                                                   const float* __restrict__ Wq,
                                                   const float* __restrict__ Wk) {
    __shared__ float As[32][68];
    __shared__ float Ws[32][132];
    const int m0 = blockIdx.x * 64;
    const int tid = threadIdx.x;
    const int tx = tid & 15;
    const int ty = tid >> 4;

    float acc[8][8];
#pragma unroll
    for (int i = 0; i < 8; i++) {
#pragma unroll
        for (int j = 0; j < 8; j++) { acc[i][j] = 0.0f; }
    }

    for (int k0 = 0; k0 < DD; k0 += 32) {
#pragma unroll
        for (int t = 0; t < 4; t++) {
            int f = tid + t * 128;
            int r = f >> 3;
            int c4 = f & 7;
            float4 v = *(const float4*)&enc[(size_t)(m0 + r) * DD + k0 + c4 * 4];
            As[c4 * 4 + 0][r] = v.x;
            As[c4 * 4 + 1][r] = v.y;
            As[c4 * 4 + 2][r] = v.z;
            As[c4 * 4 + 3][r] = v.w;
        }
#pragma unroll
        for (int t = 0; t < 8; t++) {
            int f = tid + t * 128;
            int col = f >> 3;
            int c4 = f & 7;
            const float* src;
            if (col < 64) { src = &Wq[(size_t)col * DD + k0 + c4 * 4]; }
            else          { src = &Wk[(size_t)(col - 64) * DD + k0 + c4 * 4]; }
            float4 v = *(const float4*)src;
            Ws[c4 * 4 + 0][col] = v.x;
            Ws[c4 * 4 + 1][col] = v.y;
            Ws[c4 * 4 + 2][col] = v.z;
            Ws[c4 * 4 + 3][col] = v.w;
        }
        __syncthreads();
#pragma unroll
        for (int kk = 0; kk < 32; kk++) {
            float a[8];
            float w[8];
#pragma unroll
            for (int i = 0; i < 8; i++) { a[i] = As[kk][ty * 8 + i]; }
#pragma unroll
            for (int j = 0; j < 8; j++) { w[j] = Ws[kk][tx * 8 + j]; }
#pragma unroll
            for (int i = 0; i < 8; i++) {
#pragma unroll
                for (int j = 0; j < 8; j++) { acc[i][j] = fmaf(a[i], w[j], acc[i][j]); }
            }
        }
        __syncthreads();
    }
#pragma unroll
    for (int i = 0; i < 8; i++) {
        int row = m0 + ty * 8 + i;
#pragma unroll
        for (int j = 0; j < 8; j++) {
            int col = tx * 8 + j;
            if (col < 64) { g_Q[(size_t)row * DQK + col] = acc[i][j] * 0.125f; }
            else          { g_K[(size_t)row * DQK + (col - 64)] = acc[i][j]; }
        }
    }
}

// =====================================================================
// Kernel 2: enc -> fp16 hi/lo split (one-time V conversion)
// =====================================================================
__global__ __launch_bounds__(256) void vconv_kernel(const float* __restrict__ enc) {
    const size_t n = (size_t)BB * SS * DD;
    size_t i = ((size_t)blockIdx.x * 256 + threadIdx.x) * 4;
    const size_t step = (size_t)gridDim.x * 256 * 4;
    for (; i < n; i += step) {
        float4 v = *(const float4*)&enc[i];
        __half2 h01 = __floats2half2_rn(v.x, v.y);
        __half2 h23 = __floats2half2_rn(v.z, v.w);
        float2 r01 = __half22float2(h01);
        float2 r23 = __half22float2(h23);
        __half2 l01 = __floats2half2_rn(v.x - r01.x, v.y - r01.y);
        __half2 l23 = __floats2half2_rn(v.z - r23.x, v.w - r23.y);
        *(__half2*)&g_Vh[i] = h01;
        *(__half2*)&g_Vh[i + 2] = h23;
        *(__half2*)&g_Vl[i] = l01;
        *(__half2*)&g_Vl[i + 2] = l23;
    }
}

// =====================================================================
// Kernel 3: scores -> P~ = exp(s) fp16 (unnormalized, no max needed)
// + row sums l.  Masked entries -> exp(-1e9) = 0.  128-padded span.
// =====================================================================
__global__ __launch_bounds__(256) void score_kernel() {
    const int qt = (int)gridDim.x - 1 - (int)blockIdx.x;
    const int b = blockIdx.y;
    const int q0 = qt * 64;
    const int tid = threadIdx.x;
    const int tx = tid & 15;
    const int ty = tid >> 4;

    __shared__ float Qs[64][68];
    __shared__ float Ks[64][68];
    __shared__ float red_l[64][16];

#pragma unroll
    for (int t = 0; t < 4; t++) {
        int f = tid + t * 256;
        int r = f >> 4;
        int e4 = f & 15;
        float4 v = *(const float4*)&g_Q[(size_t)(b * SS + q0 + r) * DQK + e4 * 4];
        Qs[e4 * 4 + 0][r] = v.x;
        Qs[e4 * 4 + 1][r] = v.y;
        Qs[e4 * 4 + 2][r] = v.z;
        Qs[e4 * 4 + 3][r] = v.w;
    }

    float l_i[4];
#pragma unroll
    for (int i = 0; i < 4; i++) { l_i[i] = 0.0f; }

    const int kt_end = (qt | 1);
    for (int kt = 0; kt <= kt_end; kt++) {
        const int k0 = kt * 64;
        __syncthreads();
#pragma unroll
        for (int t = 0; t < 4; t++) {
            int f = tid + t * 256;
            int r = f >> 4;
            int e4 = f & 15;
            float4 v = *(const float4*)&g_K[(size_t)(b * SS + k0 + r) * DQK + e4 * 4];
            Ks[e4 * 4 + 0][r] = v.x;
            Ks[e4 * 4 + 1][r] = v.y;
            Ks[e4 * 4 + 2][r] = v.z;
            Ks[e4 * 4 + 3][r] = v.w;
        }
        __syncthreads();

        float acc[4][4];
#pragma unroll
        for (int i = 0; i < 4; i++) {
#pragma unroll
            for (int j = 0; j < 4; j++) { acc[i][j] = 0.0f; }
        }

#pragma unroll
        for (int e = 0; e < 64; e++) {
            float4 a = *(const float4*)&Qs[e][ty * 4];
            float4 kb = *(const float4*)&Ks[e][tx * 4];
            float av[4];
            float bv[4];
            av[0] = a.x; av[1] = a.y; av[2] = a.z; av[3] = a.w;
            bv[0] = kb.x; bv[1] = kb.y; bv[2] = kb.z; bv[3] = kb.w;
#pragma unroll
            for (int i = 0; i < 4; i++) {
#pragma unroll
                for (int j = 0; j < 4; j++) { acc[i][j] = fmaf(av[i], bv[j], acc[i][j]); }
            }
        }

#pragma unroll
        for (int i = 0; i < 4; i++) {
            const int q = q0 + ty * 4 + i;
            float pv[4];
#pragma unroll
            for (int j = 0; j < 4; j++) {
                int kj = k0 + tx * 4 + j;
                float s = (kj <= q) ? acc[i][j] : -1e9f;
                pv[j] = fexp(s);
            }
            l_i[i] += (pv[0] + pv[1]) + (pv[2] + pv[3]);
            __half2 h01 = __floats2half2_rn(pv[0], pv[1]);
            __half2 h23 = __floats2half2_rn(pv[2], pv[3]);
            __half* dst = &g_Ph[((size_t)(b * SS + q)) * SS + k0 + tx * 4];
            *(__half2*)&dst[0] = h01;
            *(__half2*)&dst[2] = h23;
        }
    }

#pragma unroll
    for (int i = 0; i < 4; i++) {
        red_l[ty * 4 + i][tx] = l_i[i];
    }
    __syncthreads();
    if (tid < 64) {
        int row = tid;
        float L = 0.0f;
#pragma unroll
        for (int t = 0; t < 16; t++) { L += red_l[row][t]; }
        g_l[b * SS + q0 + row] = L;
    }
}

// =====================================================================
// Kernel 4: tensor-core PV.  O = (P~ @ (Vh + Vl)) * (1/l), cp.async pipe.
// =====================================================================
#define PSTR 40     // halfs per P smem row (80 B)
#define VSTR 136    // halfs per V smem row (272 B)
#define PV_SMEM_BYTES 55296

__device__ __forceinline__ void cp16(uint32_t dst, const void* src) {
    asm volatile(
        "{\n\t"
        ".reg .u64 gp;\n\t"
        "cvta.to.global.u64 gp, %1;\n\t"
        "cp.async.ca.shared.global [%0], [gp], 16;\n\t"
        "}"
        :: "r"(dst), "l"(src) : "memory");
}

__device__ __forceinline__ void ldsm4(uint32_t* r, const void* p) {
    uint32_t a = (uint32_t)__cvta_generic_to_shared(p);
    asm volatile("ldmatrix.sync.aligned.m8n8.x4.shared.b16 {%0,%1,%2,%3}, [%4];"
                 : "=r"(r[0]), "=r"(r[1]), "=r"(r[2]), "=r"(r[3])
                 : "r"(a));
}

__device__ __forceinline__ void ldsm4t(uint32_t* r, const void* p) {
    uint32_t a = (uint32_t)__cvta_generic_to_shared(p);
    asm volatile("ldmatrix.sync.aligned.m8n8.x4.trans.shared.b16 {%0,%1,%2,%3}, [%4];"
                 : "=r"(r[0]), "=r"(r[1]), "=r"(r[2]), "=r"(r[3])
                 : "r"(a));
}

__device__ __forceinline__ void mma_f16(float* c, const uint32_t* a,
                                        uint32_t b0, uint32_t b1) {
    asm volatile(
        "mma.sync.aligned.m16n8k16.row.col.f32.f16.f16.f32 "
        "{%0,%1,%2,%3}, {%4,%5,%6,%7}, {%8,%9}, {%0,%1,%2,%3};"
        : "+f"(c[0]), "+f"(c[1]), "+f"(c[2]), "+f"(c[3])
        : "r"(a[0]), "r"(a[1]), "r"(a[2]), "r"(a[3]), "r"(b0), "r"(b1));
}

__device__ __forceinline__ void pv_load_stage(uint32_t smb, int st, int tid,
                                              const __half* gP,
                                              const __half* gVh,
                                              const __half* gVl) {
    const int pr = tid >> 1;
    const int pc = (tid & 1) * 16;
    uint32_t dP = smb + (uint32_t)((st * 5120 + pr * PSTR + pc) * 2);
    cp16(dP, gP + (size_t)pr * SS + pc);
    cp16(dP + 16, gP + (size_t)pr * SS + pc + 8);
    const int vk = tid >> 3;
    const int vc = (tid & 7) * 16;
    uint32_t dVh = smb + (uint32_t)((10240 + st * 4352 + vk * VSTR + vc) * 2);
    cp16(dVh, gVh + (size_t)vk * DD + vc);
    cp16(dVh + 16, gVh + (size_t)vk * DD + vc + 8);
    uint32_t dVl = smb + (uint32_t)((18944 + st * 4352 + vk * VSTR + vc) * 2);
    cp16(dVl, gVl + (size_t)vk * DD + vc);
    cp16(dVl + 16, gVl + (size_t)vk * DD + vc + 8);
}

__global__ __launch_bounds__(256, 2) void pv_kernel(float* __restrict__ out) {
    extern __shared__ __half sm[];
    const int ct = blockIdx.x;
    const int rt = (int)gridDim.y - 1 - (int)blockIdx.y;
    const int b  = blockIdx.z;
    const int q0 = rt * 128;
    const int c0 = ct * 128;
    const int tid = threadIdx.x;
    const int lane = tid & 31;
    const int wid = tid >> 5;
    const int wm = (wid & 3) * 32;
    const int wn = (wid >> 2) * 64;

    const uint32_t smb = (uint32_t)__cvta_generic_to_shared((void*)sm);

    float acc[2][8][4];
#pragma unroll
    for (int i = 0; i < 2; i++) {
#pragma unroll
        for (int j = 0; j < 8; j++) {
#pragma unroll
            for (int q = 0; q < 4; q++) { acc[i][j][q] = 0.0f; }
        }
    }

    const __half* gPbase = &g_Ph[((size_t)(b * SS + q0)) * SS];
    const __half* gVhbase = &g_Vh[((size_t)(b * SS)) * DD + c0];
    const __half* gVlbase = &g_Vl[((size_t)(b * SS)) * DD + c0];

    const int nk = (rt + 1) * 4;

    pv_load_stage(smb, 0, tid, gPbase, gVhbase, gVlbase);
    asm volatile("cp.async.commit_group;" ::: "memory");

    for (int kt = 0; kt < nk; kt++) {
        const int st = kt & 1;
        if (kt + 1 < nk) {
            const int k1 = (kt + 1) * 32;
            pv_load_stage(smb, st ^ 1, tid, gPbase + k1,
                          gVhbase + (size_t)k1 * DD, gVlbase + (size_t)k1 * DD);
            asm volatile("cp.async.commit_group;" ::: "memory");
            asm volatile("cp.async.wait_group 1;" ::: "memory");
        } else {
            asm volatile("cp.async.wait_group 0;" ::: "memory");
        }
        __syncthreads();

        const __half* sP = sm + st * 5120;
        const __half* sVh = sm + 10240 + st * 4352;
        const __half* sVl = sm + 18944 + st * 4352;

#pragma unroll
        for (int s16 = 0; s16 < 2; s16++) {
            const int arow = lane & 15;
            const int ak = s16 * 16 + (lane >> 4) * 8;
            uint32_t ah0[4];
            uint32_t ah1[4];
            ldsm4(ah0, sP + (wm + arow) * PSTR + ak);
            ldsm4(ah1, sP + (wm + 16 + arow) * PSTR + ak);

#pragma unroll
            for (int nb = 0; nb < 4; nb++) {
                const int bofs = (s16 * 16 + (lane & 15)) * VSTR
                               + wn + nb * 16 + (lane >> 4) * 8;
                uint32_t bh[4];
                uint32_t bl[4];
                ldsm4t(bh, sVh + bofs);
                ldsm4t(bl, sVl + bofs);

                float* cp0 = acc[0][nb * 2];
                float* cp1 = acc[0][nb * 2 + 1];
                float* cp2 = acc[1][nb * 2];
                float* cp3 = acc[1][nb * 2 + 1];

                mma_f16(cp0, ah0, bh[0], bh[1]);
                mma_f16(cp0, ah0, bl[0], bl[1]);
                mma_f16(cp1, ah0, bh[2], bh[3]);
                mma_f16(cp1, ah0, bl[2], bl[3]);
                mma_f16(cp2, ah1, bh[0], bh[1]);
                mma_f16(cp2, ah1, bl[0], bl[1]);
                mma_f16(cp3, ah1, bh[2], bh[3]);
                mma_f16(cp3, ah1, bl[2], bl[3]);
            }
        }
        __syncthreads();
    }

    // epilogue: normalize by 1/l and store
#pragma unroll
    for (int mi = 0; mi < 2; mi++) {
        const int r0 = q0 + wm + mi * 16 + (lane >> 2);
        const float il0 = __fdividef(1.0f, g_l[b * SS + r0]);
        const float il1 = __fdividef(1.0f, g_l[b * SS + r0 + 8]);
#pragma unroll
        for (int nb8 = 0; nb8 < 8; nb8++) {
            const int cc = c0 + wn + nb8 * 8 + (lane & 3) * 2;
            float2* o0 = (float2*)&out[((size_t)(b * SS + r0)) * DD + cc];
            float2* o1 = (float2*)&out[((size_t)(b * SS + r0 + 8)) * DD + cc];
            o0->x = acc[mi][nb8][0] * il0;
            o0->y = acc[mi][nb8][1] * il0;
            o1->x = acc[mi][nb8][2] * il1;
            o1->y = acc[mi][nb8][3] * il1;
        }
    }
}

// =====================================================================
extern "C" void kernel_launch(void* const* d_in, const int* in_sizes, int n_in,
                              void* d_out, int out_size) {
    (void)in_sizes; (void)n_in; (void)out_size;
    const float* enc = (const float*)d_in[0];
    const float* Wq  = (const float*)d_in[1];
    const float* Wk  = (const float*)d_in[2];
    float* out = (float*)d_out;

    cudaFuncSetAttribute(pv_kernel, cudaFuncAttributeMaxDynamicSharedMemorySize,
                         PV_SMEM_BYTES);

    proj_kernel<<<256, 128>>>(enc, Wq, Wk);
    vconv_kernel<<<1024, 256>>>(enc);
    score_kernel<<<dim3(SS / 64, BB), 256>>>();
    pv_kernel<<<dim3(DD / 128, SS / 128, BB), 256, PV_SMEM_BYTES>>>(out);
}

// round 12
// speedup vs baseline: 2.3108x; 1.3099x over previous
#include <cuda_runtime.h>
#include <cuda_fp16.h>
#include <cstdint>
#include <math.h>

#define BB 4
#define SS 4096
#define DD 1024
#define DQK 64
#define MM (BB * SS)          // 16384 rows

// ---------------- scratch (alloc-free: __device__ globals) ----------------
static __device__ __half g_Ph[(size_t)BB * SS * SS];    // 134 MB unnormalized exp(s) fp16
static __device__ __half g_Vh[(size_t)MM * DD];         // enc hi fp16 (also proj A)
static __device__ __half g_Vl[(size_t)MM * DD];         // enc lo fp16
static __device__ __half g_Wh[128 * DD];                // W concat (Q|K) hi
static __device__ __half g_Wl[128 * DD];                // W concat lo
static __device__ __half g_Qh[(size_t)MM * DQK];        // Q hi (pre-scaled 1/8)
static __device__ __half g_Ql[(size_t)MM * DQK];
static __device__ __half g_Kh[(size_t)MM * DQK];
static __device__ __half g_Kl[(size_t)MM * DQK];
static __device__ float  g_l[MM];                       // row sums

// fast exp on the fma/alu pipes (no MUFU)
__device__ __forceinline__ float fexp(float x) {
    float t = fmaxf(x, -80.0f) * 1.44269504f;
    float f = rintf(t);
    float r = t - f;
    float p = 1.0f + r * (0.69314718f + r * (0.24022651f + r * (0.05550411f
                  + r * (0.00961813f + r * 0.00133336f))));
    int e = (int)f;
    uint32_t bits = (uint32_t)(e + 127) << 23;
    return p * __uint_as_float(bits);
}

// ---------------- shared PTX helpers ----------------
__device__ __forceinline__ void cp16(uint32_t dst, const void* src) {
    asm volatile(
        "{\n\t"
        ".reg .u64 gp;\n\t"
        "cvta.to.global.u64 gp, %1;\n\t"
        "cp.async.ca.shared.global [%0], [gp], 16;\n\t"
        "}"
        :: "r"(dst), "l"(src) : "memory");
}
__device__ __forceinline__ void cpcommit() {
    asm volatile("cp.async.commit_group;" ::: "memory");
}
__device__ __forceinline__ void cpwait0() {
    asm volatile("cp.async.wait_group 0;" ::: "memory");
}
__device__ __forceinline__ void cpwait1() {
    asm volatile("cp.async.wait_group 1;" ::: "memory");
}

__device__ __forceinline__ void ldsm4(uint32_t* r, const void* p) {
    uint32_t a = (uint32_t)__cvta_generic_to_shared(p);
    asm volatile("ldmatrix.sync.aligned.m8n8.x4.shared.b16 {%0,%1,%2,%3}, [%4];"
                 : "=r"(r[0]), "=r"(r[1]), "=r"(r[2]), "=r"(r[3])
                 : "r"(a));
}
__device__ __forceinline__ void ldsm4t(uint32_t* r, const void* p) {
    uint32_t a = (uint32_t)__cvta_generic_to_shared(p);
    asm volatile("ldmatrix.sync.aligned.m8n8.x4.trans.shared.b16 {%0,%1,%2,%3}, [%4];"
                 : "=r"(r[0]), "=r"(r[1]), "=r"(r[2]), "=r"(r[3])
                 : "r"(a));
}
__device__ __forceinline__ void mma_f16(float* c, const uint32_t* a,
                                        uint32_t b0, uint32_t b1) {
    asm volatile(
        "mma.sync.aligned.m16n8k16.row.col.f32.f16.f16.f32 "
        "{%0,%1,%2,%3}, {%4,%5,%6,%7}, {%8,%9}, {%0,%1,%2,%3};"
        : "+f"(c[0]), "+f"(c[1]), "+f"(c[2]), "+f"(c[3])
        : "r"(a[0]), "r"(a[1]), "r"(a[2]), "r"(a[3]), "r"(b0), "r"(b1));
}

// =====================================================================
// Kernel 1: enc -> fp16 hi/lo
// =====================================================================
__global__ __launch_bounds__(256) void vconv_kernel(const float* __restrict__ enc) {
    const size_t n = (size_t)MM * DD;
    size_t i = ((size_t)blockIdx.x * 256 + threadIdx.x) * 4;
    const size_t step = (size_t)gridDim.x * 256 * 4;
    for (; i < n; i += step) {
        float4 v = *(const float4*)&enc[i];
        __half2 h01 = __floats2half2_rn(v.x, v.y);
        __half2 h23 = __floats2half2_rn(v.z, v.w);
        float2 r01 = __half22float2(h01);
        float2 r23 = __half22float2(h23);
        *(__half2*)&g_Vh[i] = h01;
        *(__half2*)&g_Vh[i + 2] = h23;
        *(__half2*)&g_Vl[i] = __floats2half2_rn(v.x - r01.x, v.y - r01.y);
        *(__half2*)&g_Vl[i + 2] = __floats2half2_rn(v.z - r23.x, v.w - r23.y);
    }
}

// =====================================================================
// Kernel 2: W -> fp16 hi/lo concat [128 rows: 0-63 Wq, 64-127 Wk]
// =====================================================================
__global__ __launch_bounds__(256) void wconv_kernel(const float* __restrict__ Wq,
                                                    const float* __restrict__ Wk) {
    int i = blockIdx.x * 256 + threadIdx.x;
    const int n = 128 * DD;
    for (; i < n; i += gridDim.x * 256) {
        int row = i >> 10;
        int c = i & 1023;
        float v = (row < 64) ? Wq[row * DD + c] : Wk[(row - 64) * DD + c];
        __half h = __float2half_rn(v);
        g_Wh[i] = h;
        g_Wl[i] = __float2half_rn(v - __half2float(h));
    }
}

// =====================================================================
// Kernel 3: tensor proj. [Q|K](16384x128) = enc(16384x1024) @ Wcat^T.
// 3-term fp16 mma; output fp16 hi/lo (Q pre-scaled 1/8).
// =====================================================================
#define PJSTR 40  // halfs per 32-half smem row
// half offsets: Ah st*5120, Al 10240+st*5120, Bh 20480+st*5120, Bl 30720+st*5120
#define PROJ_SMEM_BYTES 81920

__device__ __forceinline__ void proj_load(uint32_t smb, int st, int tid,
                                          int m0, int k0) {
    const int row = tid >> 1;
    const int seg = (tid & 1) * 16;
    uint32_t dA = smb + (uint32_t)((st * 5120 + row * PJSTR + seg) * 2);
    const __half* sa = &g_Vh[(size_t)(m0 + row) * DD + k0 + seg];
    cp16(dA, sa);
    cp16(dA + 16, sa + 8);
    uint32_t dAl = dA + 10240 * 2;
    const __half* sal = &g_Vl[(size_t)(m0 + row) * DD + k0 + seg];
    cp16(dAl, sal);
    cp16(dAl + 16, sal + 8);
    uint32_t dB = smb + (uint32_t)((20480 + st * 5120 + row * PJSTR + seg) * 2);
    const __half* sb = &g_Wh[row * DD + k0 + seg];
    cp16(dB, sb);
    cp16(dB + 16, sb + 8);
    uint32_t dBl = dB + 10240 * 2;
    const __half* sbl = &g_Wl[row * DD + k0 + seg];
    cp16(dBl, sbl);
    cp16(dBl + 16, sbl + 8);
}

__global__ __launch_bounds__(256) void proj_kernel() {
    extern __shared__ __half sm[];
    const uint32_t smb = (uint32_t)__cvta_generic_to_shared((void*)sm);
    const int m0 = blockIdx.x * 128;
    const int tid = threadIdx.x;
    const int lane = tid & 31;
    const int wid = tid >> 5;
    const int wm = (wid & 3) * 32;
    const int wn = (wid >> 2) * 64;

    float acc[2][8][4];
#pragma unroll
    for (int i = 0; i < 2; i++)
#pragma unroll
        for (int j = 0; j < 8; j++)
#pragma unroll
            for (int q = 0; q < 4; q++) acc[i][j][q] = 0.0f;

    proj_load(smb, 0, tid, m0, 0);
    cpcommit();

    const int nk = DD / 32;
    for (int kt = 0; kt < nk; kt++) {
        const int st = kt & 1;
        if (kt + 1 < nk) {
            proj_load(smb, st ^ 1, tid, m0, (kt + 1) * 32);
            cpcommit();
            cpwait1();
        } else {
            cpwait0();
        }
        __syncthreads();

        const __half* sAh = sm + st * 5120;
        const __half* sAl = sm + 10240 + st * 5120;
        const __half* sBh = sm + 20480 + st * 5120;
        const __half* sBl = sm + 30720 + st * 5120;

#pragma unroll
        for (int k16 = 0; k16 < 2; k16++) {
            const int kc = k16 * 16 + (lane >> 4) * 8;
            const int arow = lane & 15;
            uint32_t ah0[4], ah1[4], al0[4], al1[4];
            ldsm4(ah0, sAh + (wm + arow) * PJSTR + kc);
            ldsm4(ah1, sAh + (wm + 16 + arow) * PJSTR + kc);
            ldsm4(al0, sAl + (wm + arow) * PJSTR + kc);
            ldsm4(al1, sAl + (wm + 16 + arow) * PJSTR + kc);
#pragma unroll
            for (int n16 = 0; n16 < 4; n16++) {
                uint32_t bh[4], bl[4];
                ldsm4(bh, sBh + (wn + n16 * 16 + arow) * PJSTR + kc);
                ldsm4(bl, sBl + (wn + n16 * 16 + arow) * PJSTR + kc);
                float* c0 = acc[0][n16 * 2];
                float* c1 = acc[0][n16 * 2 + 1];
                float* c2 = acc[1][n16 * 2];
                float* c3 = acc[1][n16 * 2 + 1];
                mma_f16(c0, ah0, bh[0], bh[2]);
                mma_f16(c0, al0, bh[0], bh[2]);
                mma_f16(c0, ah0, bl[0], bl[2]);
                mma_f16(c1, ah0, bh[1], bh[3]);
                mma_f16(c1, al0, bh[1], bh[3]);
                mma_f16(c1, ah0, bl[1], bl[3]);
                mma_f16(c2, ah1, bh[0], bh[2]);
                mma_f16(c2, al1, bh[0], bh[2]);
                mma_f16(c2, ah1, bl[0], bl[2]);
                mma_f16(c3, ah1, bh[1], bh[3]);
                mma_f16(c3, al1, bh[1], bh[3]);
                mma_f16(c3, ah1, bl[1], bl[3]);
            }
        }
        __syncthreads();
    }

    // epilogue: scale (Q cols only), split hi/lo, store
    const float scale = (wn == 0) ? 0.125f : 1.0f;
#pragma unroll
    for (int mi = 0; mi < 2; mi++) {
#pragma unroll
        for (int h = 0; h < 2; h++) {
            const int m = m0 + wm + mi * 16 + (lane >> 2) + h * 8;
#pragma unroll
            for (int nb = 0; nb < 8; nb++) {
                const int col = wn + nb * 8 + (lane & 3) * 2;
                float v0 = acc[mi][nb][h * 2 + 0] * scale;
                float v1 = acc[mi][nb][h * 2 + 1] * scale;
                __half2 hi = __floats2half2_rn(v0, v1);
                float2 hf = __half22float2(hi);
                __half2 lo = __floats2half2_rn(v0 - hf.x, v1 - hf.y);
                if (wn == 0) {
                    *(__half2*)&g_Qh[(size_t)m * DQK + col] = hi;
                    *(__half2*)&g_Ql[(size_t)m * DQK + col] = lo;
                } else {
                    *(__half2*)&g_Kh[(size_t)m * DQK + col - 64] = hi;
                    *(__half2*)&g_Kl[(size_t)m * DQK + col - 64] = lo;
                }
            }
        }
    }
}

// =====================================================================
// Kernel 4: tensor score. P~ = exp(Q@K^T) fp16 + row sums.
// 128 q-rows per block, loops causal 128-key tiles, K double-buffered.
// =====================================================================
#define SCSTR 72  // halfs per 64-half smem row (144 B, conflict-free)
// half offsets: Qh 0, Ql 9216, Kh[st] 18432+st*18432, Kl[st] 27648+st*18432
#define SCORE_SMEM_BYTES 112640

__device__ __forceinline__ void score_load_k(uint32_t smb, int st, int tid,
                                             int gk0) {
    const int row = tid >> 1;
    const int seg = (tid & 1) * 32;
    uint32_t dKh = smb + (uint32_t)((18432 + st * 18432 + row * SCSTR + seg) * 2);
    const __half* sh = &g_Kh[(size_t)(gk0 + row) * DQK + seg];
    cp16(dKh, sh);
    cp16(dKh + 16, sh + 8);
    cp16(dKh + 32, sh + 16);
    cp16(dKh + 48, sh + 24);
    uint32_t dKl = dKh + 9216 * 2;
    const __half* sl = &g_Kl[(size_t)(gk0 + row) * DQK + seg];
    cp16(dKl, sl);
    cp16(dKl + 16, sl + 8);
    cp16(dKl + 32, sl + 16);
    cp16(dKl + 48, sl + 24);
}

__global__ __launch_bounds__(256) void score_kernel() {
    extern __shared__ __half sm[];
    const uint32_t smb = (uint32_t)__cvta_generic_to_shared((void*)sm);
    float* red = (float*)(sm + 55296);

    const int qt = (int)gridDim.x - 1 - (int)blockIdx.x;   // heavy first
    const int b = blockIdx.y;
    const int q0 = qt * 128;
    const int gq0 = b * SS + q0;
    const int tid = threadIdx.x;
    const int lane = tid & 31;
    const int wid = tid >> 5;
    const int wm = (wid & 3) * 32;
    const int wn = (wid >> 2) * 64;

    // load resident Q (hi/lo)
    {
        const int row = tid >> 1;
        const int seg = (tid & 1) * 32;
        uint32_t dQh = smb + (uint32_t)((row * SCSTR + seg) * 2);
        const __half* sh = &g_Qh[(size_t)(gq0 + row) * DQK + seg];
        cp16(dQh, sh);
        cp16(dQh + 16, sh + 8);
        cp16(dQh + 32, sh + 16);
        cp16(dQh + 48, sh + 24);
        uint32_t dQl = dQh + 9216 * 2;
        const __half* sl = &g_Ql[(size_t)(gq0 + row) * DQK + seg];
        cp16(dQl, sl);
        cp16(dQl + 16, sl + 8);
        cp16(dQl + 32, sl + 16);
        cp16(dQl + 48, sl + 24);
    }
    score_load_k(smb, 0, tid, b * SS);
    cpcommit();

    float rowsum[2][2];
    rowsum[0][0] = 0.0f; rowsum[0][1] = 0.0f;
    rowsum[1][0] = 0.0f; rowsum[1][1] = 0.0f;

    const __half* sQh = sm;
    const __half* sQl = sm + 9216;

    for (int kt = 0; kt <= qt; kt++) {
        const int st = kt & 1;
        if (kt + 1 <= qt) {
            score_load_k(smb, st ^ 1, tid, b * SS + (kt + 1) * 128);
            cpcommit();
            cpwait1();
        } else {
            cpwait0();
        }
        __syncthreads();

        const __half* sKh = sm + 18432 + st * 18432;
        const __half* sKl = sKh + 9216;

        float acc[2][8][4];
#pragma unroll
        for (int i = 0; i < 2; i++)
#pragma unroll
            for (int j = 0; j < 8; j++)
#pragma unroll
                for (int q = 0; q < 4; q++) acc[i][j][q] = 0.0f;

#pragma unroll
        for (int k16 = 0; k16 < 4; k16++) {
            const int kc = k16 * 16 + (lane >> 4) * 8;
            const int arow = lane & 15;
            uint32_t ah0[4], ah1[4], al0[4], al1[4];
            ldsm4(ah0, sQh + (wm + arow) * SCSTR + kc);
            ldsm4(ah1, sQh + (wm + 16 + arow) * SCSTR + kc);
            ldsm4(al0, sQl + (wm + arow) * SCSTR + kc);
            ldsm4(al1, sQl + (wm + 16 + arow) * SCSTR + kc);
#pragma unroll
            for (int n16 = 0; n16 < 4; n16++) {
                uint32_t bh[4], bl[4];
                ldsm4(bh, sKh + (wn + n16 * 16 + arow) * SCSTR + kc);
                ldsm4(bl, sKl + (wn + n16 * 16 + arow) * SCSTR + kc);
                float* c0 = acc[0][n16 * 2];
                float* c1 = acc[0][n16 * 2 + 1];
                float* c2 = acc[1][n16 * 2];
                float* c3 = acc[1][n16 * 2 + 1];
                mma_f16(c0, ah0, bh[0], bh[2]);
                mma_f16(c0, al0, bh[0], bh[2]);
                mma_f16(c0, ah0, bl[0], bl[2]);
                mma_f16(c1, ah0, bh[1], bh[3]);
                mma_f16(c1, al0, bh[1], bh[3]);
                mma_f16(c1, ah0, bl[1], bl[3]);
                mma_f16(c2, ah1, bh[0], bh[2]);
                mma_f16(c2, al1, bh[0], bh[2]);
                mma_f16(c2, ah1, bl[0], bl[2]);
                mma_f16(c3, ah1, bh[1], bh[3]);
                mma_f16(c3, al1, bh[1], bh[3]);
                mma_f16(c3, ah1, bl[1], bl[3]);
            }
        }

        // epilogue: mask, exp, store fp16, accumulate row sums
        const int k0 = kt * 128;
#pragma unroll
        for (int mi = 0; mi < 2; mi++) {
            const int r0 = q0 + wm + mi * 16 + (lane >> 2);
            const int r1 = r0 + 8;
#pragma unroll
            for (int nb = 0; nb < 8; nb++) {
                const int kcol = k0 + wn + nb * 8 + (lane & 3) * 2;
                float s0 = (kcol <= r0) ? acc[mi][nb][0] : -1e9f;
                float s1 = (kcol + 1 <= r0) ? acc[mi][nb][1] : -1e9f;
                float s2 = (kcol <= r1) ? acc[mi][nb][2] : -1e9f;
                float s3 = (kcol + 1 <= r1) ? acc[mi][nb][3] : -1e9f;
                float p0 = fexp(s0);
                float p1 = fexp(s1);
                float p2 = fexp(s2);
                float p3 = fexp(s3);
                rowsum[mi][0] += p0 + p1;
                rowsum[mi][1] += p2 + p3;
                *(__half2*)&g_Ph[((size_t)(b * SS + r0)) * SS + kcol] =
                    __floats2half2_rn(p0, p1);
                *(__half2*)&g_Ph[((size_t)(b * SS + r1)) * SS + kcol] =
                    __floats2half2_rn(p2, p3);
            }
        }
        __syncthreads();
    }

    // reduce row sums: lanes with same row (lane>>2) differ in lane&3
#pragma unroll
    for (int mi = 0; mi < 2; mi++) {
#pragma unroll
        for (int h = 0; h < 2; h++) {
            float v = rowsum[mi][h];
            v += __shfl_xor_sync(0xffffffffu, v, 1);
            v += __shfl_xor_sync(0xffffffffu, v, 2);
            if ((lane & 3) == 0) {
                red[(wm + mi * 16 + (lane >> 2) + h * 8) * 2 + (wid >> 2)] = v;
            }
        }
    }
    __syncthreads();
    if (tid < 128) {
        g_l[gq0 + tid] = red[tid * 2] + red[tid * 2 + 1];
    }
}

// =====================================================================
// Kernel 5: tensor PV (unchanged from R10). O = (P~ @ (Vh+Vl)) * 1/l.
// =====================================================================
#define PSTR 40
#define VSTR 136
#define PV_SMEM_BYTES 55296

__device__ __forceinline__ void pv_load_stage(uint32_t smb, int st, int tid,
                                              const __half* gP,
                                              const __half* gVh,
                                              const __half* gVl) {
    const int pr = tid >> 1;
    const int pc = (tid & 1) * 16;
    uint32_t dP = smb + (uint32_t)((st * 5120 + pr * PSTR + pc) * 2);
    cp16(dP, gP + (size_t)pr * SS + pc);
    cp16(dP + 16, gP + (size_t)pr * SS + pc + 8);
    const int vk = tid >> 3;
    const int vc = (tid & 7) * 16;
    uint32_t dVh = smb + (uint32_t)((10240 + st * 4352 + vk * VSTR + vc) * 2);
    cp16(dVh, gVh + (size_t)vk * DD + vc);
    cp16(dVh + 16, gVh + (size_t)vk * DD + vc + 8);
    uint32_t dVl = smb + (uint32_t)((18944 + st * 4352 + vk * VSTR + vc) * 2);
    cp16(dVl, gVl + (size_t)vk * DD + vc);
    cp16(dVl + 16, gVl + (size_t)vk * DD + vc + 8);
}

__global__ __launch_bounds__(256, 2) void pv_kernel(float* __restrict__ out) {
    extern __shared__ __half sm[];
    const int ct = blockIdx.x;
    const int rt = (int)gridDim.y - 1 - (int)blockIdx.y;
    const int b  = blockIdx.z;
    const int q0 = rt * 128;
    const int c0 = ct * 128;
    const int tid = threadIdx.x;
    const int lane = tid & 31;
    const int wid = tid >> 5;
    const int wm = (wid & 3) * 32;
    const int wn = (wid >> 2) * 64;

    const uint32_t smb = (uint32_t)__cvta_generic_to_shared((void*)sm);

    float acc[2][8][4];
#pragma unroll
    for (int i = 0; i < 2; i++)
#pragma unroll
        for (int j = 0; j < 8; j++)
#pragma unroll
            for (int q = 0; q < 4; q++) acc[i][j][q] = 0.0f;

    const __half* gPbase = &g_Ph[((size_t)(b * SS + q0)) * SS];
    const __half* gVhbase = &g_Vh[((size_t)(b * SS)) * DD + c0];
    const __half* gVlbase = &g_Vl[((size_t)(b * SS)) * DD + c0];

    const int nk = (rt + 1) * 4;

    pv_load_stage(smb, 0, tid, gPbase, gVhbase, gVlbase);
    cpcommit();

    for (int kt = 0; kt < nk; kt++) {
        const int st = kt & 1;
        if (kt + 1 < nk) {
            const int k1 = (kt + 1) * 32;
            pv_load_stage(smb, st ^ 1, tid, gPbase + k1,
                          gVhbase + (size_t)k1 * DD, gVlbase + (size_t)k1 * DD);
            cpcommit();
            cpwait1();
        } else {
            cpwait0();
        }
        __syncthreads();

        const __half* sP = sm + st * 5120;
        const __half* sVh = sm + 10240 + st * 4352;
        const __half* sVl = sm + 18944 + st * 4352;

#pragma unroll
        for (int s16 = 0; s16 < 2; s16++) {
            const int arow = lane & 15;
            const int ak = s16 * 16 + (lane >> 4) * 8;
            uint32_t ah0[4], ah1[4];
            ldsm4(ah0, sP + (wm + arow) * PSTR + ak);
            ldsm4(ah1, sP + (wm + 16 + arow) * PSTR + ak);

#pragma unroll
            for (int nb = 0; nb < 4; nb++) {
                const int bofs = (s16 * 16 + (lane & 15)) * VSTR
                               + wn + nb * 16 + (lane >> 4) * 8;
                uint32_t bh[4], bl[4];
                ldsm4t(bh, sVh + bofs);
                ldsm4t(bl, sVl + bofs);

                float* cp0 = acc[0][nb * 2];
                float* cp1 = acc[0][nb * 2 + 1];
                float* cp2 = acc[1][nb * 2];
                float* cp3 = acc[1][nb * 2 + 1];

                mma_f16(cp0, ah0, bh[0], bh[1]);
                mma_f16(cp0, ah0, bl[0], bl[1]);
                mma_f16(cp1, ah0, bh[2], bh[3]);
                mma_f16(cp1, ah0, bl[2], bl[3]);
                mma_f16(cp2, ah1, bh[0], bh[1]);
                mma_f16(cp2, ah1, bl[0], bl[1]);
                mma_f16(cp3, ah1, bh[2], bh[3]);
                mma_f16(cp3, ah1, bl[2], bl[3]);
            }
        }
        __syncthreads();
    }

#pragma unroll
    for (int mi = 0; mi < 2; mi++) {
        const int r0 = q0 + wm + mi * 16 + (lane >> 2);
        const float il0 = __fdividef(1.0f, g_l[b * SS + r0]);
        const float il1 = __fdividef(1.0f, g_l[b * SS + r0 + 8]);
#pragma unroll
        for (int nb8 = 0; nb8 < 8; nb8++) {
            const int cc = c0 + wn + nb8 * 8 + (lane & 3) * 2;
            float2* o0 = (float2*)&out[((size_t)(b * SS + r0)) * DD + cc];
            float2* o1 = (float2*)&out[((size_t)(b * SS + r0 + 8)) * DD + cc];
            o0->x = acc[mi][nb8][0] * il0;
            o0->y = acc[mi][nb8][1] * il0;
            o1->x = acc[mi][nb8][2] * il1;
            o1->y = acc[mi][nb8][3] * il1;
        }
    }
}

// =====================================================================
extern "C" void kernel_launch(void* const* d_in, const int* in_sizes, int n_in,
                              void* d_out, int out_size) {
    (void)in_sizes; (void)n_in; (void)out_size;
    const float* enc = (const float*)d_in[0];
    const float* Wq  = (const float*)d_in[1];
    const float* Wk  = (const float*)d_in[2];
    float* out = (float*)d_out;

    cudaFuncSetAttribute(proj_kernel, cudaFuncAttributeMaxDynamicSharedMemorySize,
                         PROJ_SMEM_BYTES);
    cudaFuncSetAttribute(score_kernel, cudaFuncAttributeMaxDynamicSharedMemorySize,
                         SCORE_SMEM_BYTES);
    cudaFuncSetAttribute(pv_kernel, cudaFuncAttributeMaxDynamicSharedMemorySize,
                         PV_SMEM_BYTES);

    vconv_kernel<<<1024, 256>>>(enc);
    wconv_kernel<<<128, 256>>>(Wq, Wk);
    proj_kernel<<<MM / 128, 256, PROJ_SMEM_BYTES>>>();
    score_kernel<<<dim3(SS / 128, BB), 256, SCORE_SMEM_BYTES>>>();
    pv_kernel<<<dim3(DD / 128, SS / 128, BB), 256, PV_SMEM_BYTES>>>(out);
}

// round 15
// speedup vs baseline: 3.7217x; 1.6106x over previous
#include <cuda_runtime.h>
#include <cuda_fp16.h>
#include <cstdint>
#include <math.h>

#define BB 4
#define SS 4096
#define DD 1024
#define DQK 64
#define MM (BB * SS)          // 16384 rows

// ---------------- scratch (alloc-free: __device__ globals) ----------------
static __device__ __half g_Ph[(size_t)BB * SS * SS];    // 134 MB unnormalized exp(s) fp16
static __device__ __half g_Vh[(size_t)MM * DD];         // enc hi fp16 (also proj A)
static __device__ __half g_Vl[(size_t)MM * DD];         // enc lo fp16 (proj only)
static __device__ __half g_Wh[128 * DD];                // W concat (Q|K) hi
static __device__ __half g_Wl[128 * DD];                // W concat lo
static __device__ __half g_Qh[(size_t)MM * DQK];        // Q hi (pre-scaled 1/8)
static __device__ __half g_Ql[(size_t)MM * DQK];
static __device__ __half g_Kh[(size_t)MM * DQK];
static __device__ __half g_Kl[(size_t)MM * DQK];
static __device__ float  g_l[MM];                       // row sums (atomic)

// fast exp on the fma/alu pipes (no MUFU)
__device__ __forceinline__ float fexp(float x) {
    float t = fmaxf(x, -80.0f) * 1.44269504f;
    float f = rintf(t);
    float r = t - f;
    float p = 1.0f + r * (0.69314718f + r * (0.24022651f + r * (0.05550411f
                  + r * (0.00961813f + r * 0.00133336f))));
    int e = (int)f;
    uint32_t bits = (uint32_t)(e + 127) << 23;
    return p * __uint_as_float(bits);
}

// ---------------- shared PTX helpers ----------------
__device__ __forceinline__ void cp16(uint32_t dst, const void* src) {
    asm volatile(
        "{\n\t"
        ".reg .u64 gp;\n\t"
        "cvta.to.global.u64 gp, %1;\n\t"
        "cp.async.ca.shared.global [%0], [gp], 16;\n\t"
        "}"
        :: "r"(dst), "l"(src) : "memory");
}
__device__ __forceinline__ void cpcommit() {
    asm volatile("cp.async.commit_group;" ::: "memory");
}
__device__ __forceinline__ void cpwait0() {
    asm volatile("cp.async.wait_group 0;" ::: "memory");
}
__device__ __forceinline__ void cpwait1() {
    asm volatile("cp.async.wait_group 1;" ::: "memory");
}

__device__ __forceinline__ void ldsm4(uint32_t* r, const void* p) {
    uint32_t a = (uint32_t)__cvta_generic_to_shared(p);
    asm volatile("ldmatrix.sync.aligned.m8n8.x4.shared.b16 {%0,%1,%2,%3}, [%4];"
                 : "=r"(r[0]), "=r"(r[1]), "=r"(r[2]), "=r"(r[3])
                 : "r"(a));
}
__device__ __forceinline__ void ldsm4t(uint32_t* r, const void* p) {
    uint32_t a = (uint32_t)__cvta_generic_to_shared(p);
    asm volatile("ldmatrix.sync.aligned.m8n8.x4.trans.shared.b16 {%0,%1,%2,%3}, [%4];"
                 : "=r"(r[0]), "=r"(r[1]), "=r"(r[2]), "=r"(r[3])
                 : "r"(a));
}
__device__ __forceinline__ void mma_f16(float* c, const uint32_t* a,
                                        uint32_t b0, uint32_t b1) {
    asm volatile(
        "mma.sync.aligned.m16n8k16.row.col.f32.f16.f16.f32 "
        "{%0,%1,%2,%3}, {%4,%5,%6,%7}, {%8,%9}, {%0,%1,%2,%3};"
        : "+f"(c[0]), "+f"(c[1]), "+f"(c[2]), "+f"(c[3])
        : "r"(a[0]), "r"(a[1]), "r"(a[2]), "r"(a[3]), "r"(b0), "r"(b1));
}

// =====================================================================
// Kernel 1: enc -> fp16 hi/lo  (also zeroes g_l)
// =====================================================================
__global__ __launch_bounds__(256) void vconv_kernel(const float* __restrict__ enc) {
    const int gtid = blockIdx.x * 256 + threadIdx.x;
    if (gtid < MM) { g_l[gtid] = 0.0f; }
    const size_t n = (size_t)MM * DD;
    size_t i = ((size_t)gtid) * 4;
    const size_t step = (size_t)gridDim.x * 256 * 4;
    for (; i < n; i += step) {
        float4 v = *(const float4*)&enc[i];
        __half2 h01 = __floats2half2_rn(v.x, v.y);
        __half2 h23 = __floats2half2_rn(v.z, v.w);
        float2 r01 = __half22float2(h01);
        float2 r23 = __half22float2(h23);
        *(__half2*)&g_Vh[i] = h01;
        *(__half2*)&g_Vh[i + 2] = h23;
        *(__half2*)&g_Vl[i] = __floats2half2_rn(v.x - r01.x, v.y - r01.y);
        *(__half2*)&g_Vl[i + 2] = __floats2half2_rn(v.z - r23.x, v.w - r23.y);
    }
}

// =====================================================================
// Kernel 2: W -> fp16 hi/lo concat [128 rows: 0-63 Wq, 64-127 Wk]
// =====================================================================
__global__ __launch_bounds__(256) void wconv_kernel(const float* __restrict__ Wq,
                                                    const float* __restrict__ Wk) {
    int i = blockIdx.x * 256 + threadIdx.x;
    const int n = 128 * DD;
    for (; i < n; i += gridDim.x * 256) {
        int row = i >> 10;
        int c = i & 1023;
        float v = (row < 64) ? Wq[row * DD + c] : Wk[(row - 64) * DD + c];
        __half h = __float2half_rn(v);
        g_Wh[i] = h;
        g_Wl[i] = __float2half_rn(v - __half2float(h));
    }
}

// =====================================================================
// Kernel 3: tensor proj. [Q|K](16384x128) = enc(16384x1024) @ Wcat^T.
// =====================================================================
#define PJSTR 40
#define PROJ_SMEM_BYTES 81920

__device__ __forceinline__ void proj_load(uint32_t smb, int st, int tid,
                                          int m0, int k0) {
    const int row = tid >> 1;
    const int seg = (tid & 1) * 16;
    uint32_t dA = smb + (uint32_t)((st * 5120 + row * PJSTR + seg) * 2);
    const __half* sa = &g_Vh[(size_t)(m0 + row) * DD + k0 + seg];
    cp16(dA, sa);
    cp16(dA + 16, sa + 8);
    uint32_t dAl = dA + 10240 * 2;
    const __half* sal = &g_Vl[(size_t)(m0 + row) * DD + k0 + seg];
    cp16(dAl, sal);
    cp16(dAl + 16, sal + 8);
    uint32_t dB = smb + (uint32_t)((20480 + st * 5120 + row * PJSTR + seg) * 2);
    const __half* sb = &g_Wh[row * DD + k0 + seg];
    cp16(dB, sb);
    cp16(dB + 16, sb + 8);
    uint32_t dBl = dB + 10240 * 2;
    const __half* sbl = &g_Wl[row * DD + k0 + seg];
    cp16(dBl, sbl);
    cp16(dBl + 16, sbl + 8);
}

__global__ __launch_bounds__(256) void proj_kernel() {
    extern __shared__ __half sm[];
    const uint32_t smb = (uint32_t)__cvta_generic_to_shared((void*)sm);
    const int m0 = blockIdx.x * 128;
    const int tid = threadIdx.x;
    const int lane = tid & 31;
    const int wid = tid >> 5;
    const int wm = (wid & 3) * 32;
    const int wn = (wid >> 2) * 64;

    float acc[2][8][4];
#pragma unroll
    for (int i = 0; i < 2; i++)
#pragma unroll
        for (int j = 0; j < 8; j++)
#pragma unroll
            for (int q = 0; q < 4; q++) acc[i][j][q] = 0.0f;

    proj_load(smb, 0, tid, m0, 0);
    cpcommit();

    const int nk = DD / 32;
    for (int kt = 0; kt < nk; kt++) {
        const int st = kt & 1;
        if (kt + 1 < nk) {
            proj_load(smb, st ^ 1, tid, m0, (kt + 1) * 32);
            cpcommit();
            cpwait1();
        } else {
            cpwait0();
        }
        __syncthreads();

        const __half* sAh = sm + st * 5120;
        const __half* sAl = sm + 10240 + st * 5120;
        const __half* sBh = sm + 20480 + st * 5120;
        const __half* sBl = sm + 30720 + st * 5120;

#pragma unroll
        for (int k16 = 0; k16 < 2; k16++) {
            const int kc = k16 * 16 + (lane >> 4) * 8;
            const int arow = lane & 15;
            uint32_t ah0[4], ah1[4], al0[4], al1[4];
            ldsm4(ah0, sAh + (wm + arow) * PJSTR + kc);
            ldsm4(ah1, sAh + (wm + 16 + arow) * PJSTR + kc);
            ldsm4(al0, sAl + (wm + arow) * PJSTR + kc);
            ldsm4(al1, sAl + (wm + 16 + arow) * PJSTR + kc);
#pragma unroll
            for (int n16 = 0; n16 < 4; n16++) {
                uint32_t bh[4], bl[4];
                ldsm4(bh, sBh + (wn + n16 * 16 + arow) * PJSTR + kc);
                ldsm4(bl, sBl + (wn + n16 * 16 + arow) * PJSTR + kc);
                float* c0 = acc[0][n16 * 2];
                float* c1 = acc[0][n16 * 2 + 1];
                float* c2 = acc[1][n16 * 2];
                float* c3 = acc[1][n16 * 2 + 1];
                mma_f16(c0, ah0, bh[0], bh[2]);
                mma_f16(c0, al0, bh[0], bh[2]);
                mma_f16(c0, ah0, bl[0], bl[2]);
                mma_f16(c1, ah0, bh[1], bh[3]);
                mma_f16(c1, al0, bh[1], bh[3]);
                mma_f16(c1, ah0, bl[1], bl[3]);
                mma_f16(c2, ah1, bh[0], bh[2]);
                mma_f16(c2, al1, bh[0], bh[2]);
                mma_f16(c2, ah1, bl[0], bl[2]);
                mma_f16(c3, ah1, bh[1], bh[3]);
                mma_f16(c3, al1, bh[1], bh[3]);
                mma_f16(c3, ah1, bl[1], bl[3]);
            }
        }
        __syncthreads();
    }

    const float scale = (wn == 0) ? 0.125f : 1.0f;
#pragma unroll
    for (int mi = 0; mi < 2; mi++) {
#pragma unroll
        for (int h = 0; h < 2; h++) {
            const int m = m0 + wm + mi * 16 + (lane >> 2) + h * 8;
#pragma unroll
            for (int nb = 0; nb < 8; nb++) {
                const int col = wn + nb * 8 + (lane & 3) * 2;
                float v0 = acc[mi][nb][h * 2 + 0] * scale;
                float v1 = acc[mi][nb][h * 2 + 1] * scale;
                __half2 hi = __floats2half2_rn(v0, v1);
                float2 hf = __half22float2(hi);
                __half2 lo = __floats2half2_rn(v0 - hf.x, v1 - hf.y);
                if (wn == 0) {
                    *(__half2*)&g_Qh[(size_t)m * DQK + col] = hi;
                    *(__half2*)&g_Ql[(size_t)m * DQK + col] = lo;
                } else {
                    *(__half2*)&g_Kh[(size_t)m * DQK + col - 64] = hi;
                    *(__half2*)&g_Kl[(size_t)m * DQK + col - 64] = lo;
                }
            }
        }
    }
}

// =====================================================================
// Kernel 4: tensor score, ONE 128x128 causal tile per block.
// grid.x = 528 tiles (kt <= qt), grid.y = batch. Row sums via atomicAdd.
// smem: Qh 0, Ql 9216, Kh 18432, Kl 27648 (halfs, stride 72)
// =====================================================================
#define SCSTR 72
#define SCORE_SMEM_BYTES 73728

__global__ __launch_bounds__(256) void score_kernel() {
    extern __shared__ __half sm[];
    const uint32_t smb = (uint32_t)__cvta_generic_to_shared((void*)sm);
    const int b = blockIdx.y;
    const int t = blockIdx.x;
    int qt = (int)((sqrtf(8.0f * (float)t + 1.0f) - 1.0f) * 0.5f);
    while ((qt + 1) * (qt + 2) / 2 <= t) { qt++; }
    while (qt * (qt + 1) / 2 > t) { qt--; }
    const int kt = t - qt * (qt + 1) / 2;

    const int q0 = qt * 128;
    const int k0 = kt * 128;
    const int gq0 = b * SS + q0;
    const int gk0 = b * SS + k0;
    const int tid = threadIdx.x;
    const int lane = tid & 31;
    const int wid = tid >> 5;
    const int wm = (wid & 3) * 32;
    const int wn = (wid >> 2) * 64;

    // stage Q + K tiles (hi/lo), 64 cols each
    {
        const int row = tid >> 1;
        const int seg = (tid & 1) * 32;
        uint32_t d0 = smb + (uint32_t)((row * SCSTR + seg) * 2);
        const __half* s0 = &g_Qh[(size_t)(gq0 + row) * DQK + seg];
        cp16(d0, s0); cp16(d0 + 16, s0 + 8); cp16(d0 + 32, s0 + 16); cp16(d0 + 48, s0 + 24);
        uint32_t d1 = d0 + 9216 * 2;
        const __half* s1 = &g_Ql[(size_t)(gq0 + row) * DQK + seg];
        cp16(d1, s1); cp16(d1 + 16, s1 + 8); cp16(d1 + 32, s1 + 16); cp16(d1 + 48, s1 + 24);
        uint32_t d2 = d0 + 18432 * 2;
        const __half* s2 = &g_Kh[(size_t)(gk0 + row) * DQK + seg];
        cp16(d2, s2); cp16(d2 + 16, s2 + 8); cp16(d2 + 32, s2 + 16); cp16(d2 + 48, s2 + 24);
        uint32_t d3 = d0 + 27648 * 2;
        const __half* s3 = &g_Kl[(size_t)(gk0 + row) * DQK + seg];
        cp16(d3, s3); cp16(d3 + 16, s3 + 8); cp16(d3 + 32, s3 + 16); cp16(d3 + 48, s3 + 24);
    }
    cpcommit();
    cpwait0();
    __syncthreads();

    const __half* sQh = sm;
    const __half* sQl = sm + 9216;
    const __half* sKh = sm + 18432;
    const __half* sKl = sm + 27648;

    float acc[2][8][4];
#pragma unroll
    for (int i = 0; i < 2; i++)
#pragma unroll
        for (int j = 0; j < 8; j++)
#pragma unroll
            for (int q = 0; q < 4; q++) acc[i][j][q] = 0.0f;

#pragma unroll
    for (int k16 = 0; k16 < 4; k16++) {
        const int kc = k16 * 16 + (lane >> 4) * 8;
        const int arow = lane & 15;
        uint32_t ah0[4], ah1[4], al0[4], al1[4];
        ldsm4(ah0, sQh + (wm + arow) * SCSTR + kc);
        ldsm4(ah1, sQh + (wm + 16 + arow) * SCSTR + kc);
        ldsm4(al0, sQl + (wm + arow) * SCSTR + kc);
        ldsm4(al1, sQl + (wm + 16 + arow) * SCSTR + kc);
#pragma unroll
        for (int n16 = 0; n16 < 4; n16++) {
            uint32_t bh[4], bl[4];
            ldsm4(bh, sKh + (wn + n16 * 16 + arow) * SCSTR + kc);
            ldsm4(bl, sKl + (wn + n16 * 16 + arow) * SCSTR + kc);
            float* c0 = acc[0][n16 * 2];
            float* c1 = acc[0][n16 * 2 + 1];
            float* c2 = acc[1][n16 * 2];
            float* c3 = acc[1][n16 * 2 + 1];
            mma_f16(c0, ah0, bh[0], bh[2]);
            mma_f16(c0, al0, bh[0], bh[2]);
            mma_f16(c0, ah0, bl[0], bl[2]);
            mma_f16(c1, ah0, bh[1], bh[3]);
            mma_f16(c1, al0, bh[1], bh[3]);
            mma_f16(c1, ah0, bl[1], bl[3]);
            mma_f16(c2, ah1, bh[0], bh[2]);
            mma_f16(c2, al1, bh[0], bh[2]);
            mma_f16(c2, ah1, bl[0], bl[2]);
            mma_f16(c3, ah1, bh[1], bh[3]);
            mma_f16(c3, al1, bh[1], bh[3]);
            mma_f16(c3, ah1, bl[1], bl[3]);
        }
    }

    // epilogue: mask, exp, store fp16, row-sum atomics
    float rowsum[2][2];
    rowsum[0][0] = 0.0f; rowsum[0][1] = 0.0f;
    rowsum[1][0] = 0.0f; rowsum[1][1] = 0.0f;

#pragma unroll
    for (int mi = 0; mi < 2; mi++) {
        const int r0 = q0 + wm + mi * 16 + (lane >> 2);
        const int r1 = r0 + 8;
#pragma unroll
        for (int nb = 0; nb < 8; nb++) {
            const int kcol = k0 + wn + nb * 8 + (lane & 3) * 2;
            float s0 = (kcol <= r0) ? acc[mi][nb][0] : -1e9f;
            float s1 = (kcol + 1 <= r0) ? acc[mi][nb][1] : -1e9f;
            float s2 = (kcol <= r1) ? acc[mi][nb][2] : -1e9f;
            float s3 = (kcol + 1 <= r1) ? acc[mi][nb][3] : -1e9f;
            float p0 = fexp(s0);
            float p1 = fexp(s1);
            float p2 = fexp(s2);
            float p3 = fexp(s3);
            rowsum[mi][0] += p0 + p1;
            rowsum[mi][1] += p2 + p3;
            *(__half2*)&g_Ph[((size_t)(b * SS + r0)) * SS + kcol] =
                __floats2half2_rn(p0, p1);
            *(__half2*)&g_Ph[((size_t)(b * SS + r1)) * SS + kcol] =
                __floats2half2_rn(p2, p3);
        }
    }

#pragma unroll
    for (int mi = 0; mi < 2; mi++) {
#pragma unroll
        for (int h = 0; h < 2; h++) {
            float v = rowsum[mi][h];
            v += __shfl_xor_sync(0xffffffffu, v, 1);
            v += __shfl_xor_sync(0xffffffffu, v, 2);
            if ((lane & 3) == 0) {
                const int row = q0 + wm + mi * 16 + (lane >> 2) + h * 8;
                atomicAdd(&g_l[b * SS + row], v);
            }
        }
    }
}

// =====================================================================
// Kernel 5: tensor PV (V hi only). O = (P~ @ Vh) * 1/l.
// smem halfs: P st*5120 (2 stages), Vh 10240+st*4352
// =====================================================================
#define PSTR 40
#define VSTR 136
#define PV_SMEM_BYTES 37888

__device__ __forceinline__ void pv_load_stage(uint32_t smb, int st, int tid,
                                              const __half* gP,
                                              const __half* gVh) {
    const int pr = tid >> 1;
    const int pc = (tid & 1) * 16;
    uint32_t dP = smb + (uint32_t)((st * 5120 + pr * PSTR + pc) * 2);
    cp16(dP, gP + (size_t)pr * SS + pc);
    cp16(dP + 16, gP + (size_t)pr * SS + pc + 8);
    const int vk = tid >> 3;
    const int vc = (tid & 7) * 16;
    uint32_t dVh = smb + (uint32_t)((10240 + st * 4352 + vk * VSTR + vc) * 2);
    cp16(dVh, gVh + (size_t)vk * DD + vc);
    cp16(dVh + 16, gVh + (size_t)vk * DD + vc + 8);
}

__global__ __launch_bounds__(256, 2) void pv_kernel(float* __restrict__ out) {
    extern __shared__ __half sm[];
    const int ct = blockIdx.x;
    const int rt = (int)gridDim.y - 1 - (int)blockIdx.y;
    const int b  = blockIdx.z;
    const int q0 = rt * 128;
    const int c0 = ct * 128;
    const int tid = threadIdx.x;
    const int lane = tid & 31;
    const int wid = tid >> 5;
    const int wm = (wid & 3) * 32;
    const int wn = (wid >> 2) * 64;

    const uint32_t smb = (uint32_t)__cvta_generic_to_shared((void*)sm);

    float acc[2][8][4];
#pragma unroll
    for (int i = 0; i < 2; i++)
#pragma unroll
        for (int j = 0; j < 8; j++)
#pragma unroll
            for (int q = 0; q < 4; q++) acc[i][j][q] = 0.0f;

    const __half* gPbase = &g_Ph[((size_t)(b * SS + q0)) * SS];
    const __half* gVhbase = &g_Vh[((size_t)(b * SS)) * DD + c0];

    const int nk = (rt + 1) * 4;

    pv_load_stage(smb, 0, tid, gPbase, gVhbase);
    cpcommit();

    for (int kt = 0; kt < nk; kt++) {
        const int st = kt & 1;
        if (kt + 1 < nk) {
            const int k1 = (kt + 1) * 32;
            pv_load_stage(smb, st ^ 1, tid, gPbase + k1,
                          gVhbase + (size_t)k1 * DD);
            cpcommit();
            cpwait1();
        } else {
            cpwait0();
        }
        __syncthreads();

        const __half* sP = sm + st * 5120;
        const __half* sVh = sm + 10240 + st * 4352;

#pragma unroll
        for (int s16 = 0; s16 < 2; s16++) {
            const int arow = lane & 15;
            const int ak = s16 * 16 + (lane >> 4) * 8;
            uint32_t ah0[4], ah1[4];
            ldsm4(ah0, sP + (wm + arow) * PSTR + ak);
            ldsm4(ah1, sP + (wm + 16 + arow) * PSTR + ak);

#pragma unroll
            for (int nb = 0; nb < 4; nb++) {
                const int bofs = (s16 * 16 + (lane & 15)) * VSTR
                               + wn + nb * 16 + (lane >> 4) * 8;
                uint32_t bh[4];
                ldsm4t(bh, sVh + bofs);

                mma_f16(acc[0][nb * 2],     ah0, bh[0], bh[1]);
                mma_f16(acc[0][nb * 2 + 1], ah0, bh[2], bh[3]);
                mma_f16(acc[1][nb * 2],     ah1, bh[0], bh[1]);
                mma_f16(acc[1][nb * 2 + 1], ah1, bh[2], bh[3]);
            }
        }
        __syncthreads();
    }

#pragma unroll
    for (int mi = 0; mi < 2; mi++) {
        const int r0 = q0 + wm + mi * 16 + (lane >> 2);
        const float il0 = __fdividef(1.0f, g_l[b * SS + r0]);
        const float il1 = __fdividef(1.0f, g_l[b * SS + r0 + 8]);
#pragma unroll
        for (int nb8 = 0; nb8 < 8; nb8++) {
            const int cc = c0 + wn + nb8 * 8 + (lane & 3) * 2;
            float2* o0 = (float2*)&out[((size_t)(b * SS + r0)) * DD + cc];
            float2* o1 = (float2*)&out[((size_t)(b * SS + r0 + 8)) * DD + cc];
            o0->x = acc[mi][nb8][0] * il0;
            o0->y = acc[mi][nb8][1] * il0;
            o1->x = acc[mi][nb8][2] * il1;
            o1->y = acc[mi][nb8][3] * il1;
        }
    }
}

// =====================================================================
extern "C" void kernel_launch(void* const* d_in, const int* in_sizes, int n_in,
                              void* d_out, int out_size) {
    (void)in_sizes; (void)n_in; (void)out_size;
    const float* enc = (const float*)d_in[0];
    const float* Wq  = (const float*)d_in[1];
    const float* Wk  = (const float*)d_in[2];
    float* out = (float*)d_out;

    cudaFuncSetAttribute(proj_kernel, cudaFuncAttributeMaxDynamicSharedMemorySize,
                         PROJ_SMEM_BYTES);
    cudaFuncSetAttribute(score_kernel, cudaFuncAttributeMaxDynamicSharedMemorySize,
                         SCORE_SMEM_BYTES);
    cudaFuncSetAttribute(pv_kernel, cudaFuncAttributeMaxDynamicSharedMemorySize,
                         PV_SMEM_BYTES);

    vconv_kernel<<<1024, 256>>>(enc);
    wconv_kernel<<<128, 256>>>(Wq, Wk);
    proj_kernel<<<MM / 128, 256, PROJ_SMEM_BYTES>>>();
    score_kernel<<<dim3((SS / 128) * (SS / 128 + 1) / 2, BB), 256, SCORE_SMEM_BYTES>>>();
    pv_kernel<<<dim3(DD / 128, SS / 128, BB), 256, PV_SMEM_BYTES>>>(out);
}